// round 17
// baseline (speedup 1.0000x reference)
#include <cuda_runtime.h>
#include <cuda_fp16.h>
#include <stdint.h>

// ---------------------------------------------------------------------------
// Problem constants
// ---------------------------------------------------------------------------
#define F0C   39
#define DC    16
#define NBB   8                  // batches per CTA (8 b x 16 d = 128 GEMM rows)
#define K0G   120                // phase-0 groups of 8 k (119 real + 1 pad)
#define K1G   312                // phase-1 groups (39 i x 8 j-blocks)
#define NGR   (K0G + K1G)        // 432 groups
#define KCH   64                 // k per chunk = 8 groups
#define NCHT  (NGR / 8)          // 54 chunks
#define CH0   (K0G / 8)          // 15 chunks in phase 0
#define KTOT  (NGR * 8)          // 3456 weight rows
#define UHSTR 120                // sUH row stride in halves (240 B)
// sUH row: cols 0..38 = u (fp16), 39..47 = zeros, 48..111 = h, 112..119 pad

// W tile in SMEM: 64 k-rows x 128 n (fp16), row padded to 272 B
#define WROWB 272
#define WBUFB (64 * WROWB)       // 17408 bytes per buffer

// SMEM layout (float-word offsets)
#define OFF_W    0               // 2 buffers x 4352 words = 8704
#define OFF_UH   8704            // 128 x 120 halves = 7680 words
#define OFF_META 16384           // 432 words
#define OFF_S    16816           // 128
#define OFF_WV   16944           // 192
#define SMEM_WORDS 17136
#define SMEM_BYTES (SMEM_WORDS * 4)   // 68544

// Fragment k-permutation: physical W row p (within 64-chunk) maps to
// group g = hs*4 + tig, position pos = ks2*4 + h2*2 + e where
// ksg=p>>4, win=p&15, tig=(win>>1)&3, e=win&1, h2=win>>3, hs=ksg>>1, ks2=ksg&1.
__device__ __align__(16) __half g_W[KTOT * 128];

// ---------------------------------------------------------------------------
// Helpers
// ---------------------------------------------------------------------------
__device__ __forceinline__ uint32_t hmul2_u32(__half2 u, uint32_t hv) {
    __half2 r = __hmul2(u, *(__half2*)&hv);
    return *(uint32_t*)&r;
}

__device__ __forceinline__ void cp_async16(void* dst, const void* src) {
    unsigned sa = (unsigned)__cvta_generic_to_shared(dst);
    asm volatile("cp.async.cg.shared.global [%0], [%1], 16;\n"
                 :: "r"(sa), "l"(src));
}

__device__ __forceinline__ void ldmx4t(uint32_t& b0, uint32_t& b1,
                                       uint32_t& b2, uint32_t& b3,
                                       uint32_t addr) {
    asm volatile(
        "ldmatrix.sync.aligned.m8n8.x4.trans.shared.b16 {%0,%1,%2,%3}, [%4];"
        : "=r"(b0), "=r"(b1), "=r"(b2), "=r"(b3) : "r"(addr));
}

__device__ __forceinline__ void mma_fp16(float* c, const uint32_t* a,
                                         uint32_t b0, uint32_t b1) {
    asm volatile(
        "mma.sync.aligned.m16n8k16.row.col.f32.f16.f16.f32 "
        "{%0,%1,%2,%3}, {%4,%5,%6,%7}, {%8,%9}, {%0,%1,%2,%3};\n"
        : "+f"(c[0]), "+f"(c[1]), "+f"(c[2]), "+f"(c[3])
        : "r"(a[0]), "r"(a[1]), "r"(a[2]), "r"(a[3]), "r"(b0), "r"(b1));
}

// group index -> (i, joff) metadata. gidx<K0G: phase-0 (i, aligned j-block);
// else phase-1 (i, h-block at 48 + 8t). Pad group -> (0, 40) (zero region).
__device__ __forceinline__ uint32_t group_meta(int gidx) {
    if (gidx < K0G) {
        int i = 0, acc = 0;
        while (i < F0C && acc + (5 - (i >> 3)) <= gidx) {
            acc += 5 - (i >> 3);
            ++i;
        }
        if (i < F0C) {
            int b = (i >> 3) + (gidx - acc);
            return ((uint32_t)i << 8) | (uint32_t)(8 * b);
        }
        return 40u;                       // pad group: i=0, joff=40 (zeros)
    }
    int g1 = gidx - K0G;
    return ((uint32_t)(g1 >> 3) << 8) | (uint32_t)(48 + (g1 & 7) * 8);
}

// ---------------------------------------------------------------------------
// Prologue: build permuted fp16 weight matrix.
// phase-0 row (i, j=8b+pos): valid iff i<=j<=38; folded f0[i,j]+f0[j,i].
// phase-1 row (i, j=8t+pos): f1[i*64+j].
// ---------------------------------------------------------------------------
__global__ void fold_weights_kernel(const float* __restrict__ f0,
                                    const float* __restrict__ f1) {
    int idx = blockIdx.x * blockDim.x + threadIdx.x;
    if (idx >= KTOT * 128) return;
    int p = idx >> 7;
    int n = idx & 127;
    int chunk = p >> 6, w64 = p & 63;
    int ksg = w64 >> 4, win = w64 & 15;
    int tig = (win >> 1) & 3, e = win & 1, h2 = win >> 3;
    int hs = ksg >> 1, ks2 = ksg & 1;
    int gidx = chunk * 8 + hs * 4 + tig;
    int pos = ks2 * 4 + h2 * 2 + e;

    float v = 0.0f;
    uint32_t meta = group_meta(gidx);
    int i = (int)(meta >> 8);
    int joff = (int)(meta & 255u);
    if (gidx < K0G) {
        int j = joff + pos;               // joff = 8b (or 40 for pad)
        if (joff < 40 && j >= i && j <= 38) {
            v = f0[(i * F0C + j) * 128 + n];
            if (j > i) v += f0[(j * F0C + i) * 128 + n];
        }
    } else {
        int j = (joff - 48) + pos;        // 0..63
        v = f1[(i * 64 + j) * 128 + n];
    }
    g_W[idx] = __float2half_rn(v);
}

// Stage one 64x128 fp16 W chunk into a 272B-stride SMEM buffer.
__device__ __forceinline__ void stage_w(int chunk, char* dst, int tid) {
#pragma unroll
    for (int it = 0; it < 4; ++it) {
        int s = tid + it * 256;          // 1024 segments of 16B
        int row = s >> 4;
        int seg = s & 15;
        cp_async16(dst + row * WROWB + seg * 16,
                   g_W + (size_t)(chunk * 64 + row) * 128 + seg * 8);
    }
}

// ---------------------------------------------------------------------------
// A-source load + fragment build (unified: u x u or u x h via meta).
// ---------------------------------------------------------------------------
struct ASrc {
    uint4 jv0, jv8, jv16, jv24;
    __half2 u0, u8, u16, u24;
};

__device__ __forceinline__ void load_src(const __half* __restrict__ sUH,
                                         int R0, uint32_t meta, ASrc& s) {
    int i = (int)(meta >> 8);
    int joff = (int)(meta & 255u);
    const __half* b0 = sUH + R0 * UHSTR;
    const __half* b8 = b0 + 8 * UHSTR;
    const __half* b16 = b0 + 16 * UHSTR;
    const __half* b24 = b0 + 24 * UHSTR;
    s.jv0  = *(const uint4*)(b0 + joff);
    s.jv8  = *(const uint4*)(b8 + joff);
    s.jv16 = *(const uint4*)(b16 + joff);
    s.jv24 = *(const uint4*)(b24 + joff);
    s.u0  = __half2half2(b0[i]);
    s.u8  = __half2half2(b8[i]);
    s.u16 = __half2half2(b16[i]);
    s.u24 = __half2half2(b24[i]);
}

__device__ __forceinline__ void build_a(const ASrc& s, uint32_t a[2][2][4]) {
    const uint32_t* w0  = (const uint32_t*)&s.jv0;
    const uint32_t* w8  = (const uint32_t*)&s.jv8;
    const uint32_t* w16 = (const uint32_t*)&s.jv16;
    const uint32_t* w24 = (const uint32_t*)&s.jv24;
#pragma unroll
    for (int ks2 = 0; ks2 < 2; ++ks2) {
#pragma unroll
        for (int h2 = 0; h2 < 2; ++h2) {
            int w = ks2 * 2 + h2;
            a[0][ks2][h2 * 2 + 0] = hmul2_u32(s.u0,  w0[w]);
            a[0][ks2][h2 * 2 + 1] = hmul2_u32(s.u8,  w8[w]);
            a[1][ks2][h2 * 2 + 0] = hmul2_u32(s.u16, w16[w]);
            a[1][ks2][h2 * 2 + 1] = hmul2_u32(s.u24, w24[w]);
        }
    }
}

// MMAs for one half-chunk (2 k-steps), B fragments double-buffered.
// wbase MUST include the per-lane ldmatrix offset (fix for R15 bug).
__device__ __forceinline__ void mma_half(uint32_t wbase, int ksg0,
                                         const uint32_t a[2][2][4],
                                         float acc[2][8][4]) {
    uint32_t b[2][4];
    ldmx4t(b[0][0], b[0][1], b[0][2], b[0][3],
           wbase + (uint32_t)ksg0 * (16 * WROWB));
#pragma unroll
    for (int idx = 0; idx < 8; ++idx) {
        int cur = idx & 1, nxt = cur ^ 1;
        if (idx < 7) {
            int ni = idx + 1;
            ldmx4t(b[nxt][0], b[nxt][1], b[nxt][2], b[nxt][3],
                   wbase + (uint32_t)(ksg0 + (ni >> 2)) * (16 * WROWB) +
                   (ni & 3) * 32);
        }
        int ks2 = idx >> 2, nt2 = idx & 3;
        mma_fp16(acc[0][nt2 * 2],     a[0][ks2], b[cur][0], b[cur][1]);
        mma_fp16(acc[1][nt2 * 2],     a[1][ks2], b[cur][0], b[cur][1]);
        mma_fp16(acc[0][nt2 * 2 + 1], a[0][ks2], b[cur][2], b[cur][3]);
        mma_fp16(acc[1][nt2 * 2 + 1], a[1][ks2], b[cur][2], b[cur][3]);
    }
}

// ---------------------------------------------------------------------------
// Main kernel: 512 CTAs x 256 threads. CTA = 8 b x 16 d = 128 GEMM rows.
// ---------------------------------------------------------------------------
__global__ void __launch_bounds__(256, 2)
cin_kernel(const float* __restrict__ x, const float* __restrict__ wv,
           const float* __restrict__ bias, float* __restrict__ out) {
    extern __shared__ __align__(16) float smem[];
    char*     sW    = (char*)(smem + OFF_W);
    __half*   sUH   = (__half*)(smem + OFF_UH);
    uint32_t* sMeta = (uint32_t*)(smem + OFF_META);
    float*    sS    = smem + OFF_S;
    float*    sWv   = smem + OFF_WV;

    int tid  = threadIdx.x;
    int lane = tid & 31;
    int warp = tid >> 5;
    int g    = lane >> 2;
    int tig  = lane & 3;
    int warp_m = warp >> 1;
    int warp_n = warp & 1;
    int b0 = blockIdx.x * NBB;
    const int R0 = warp_m * 32 + g;

    uint32_t wbase_u32 = (uint32_t)__cvta_generic_to_shared(sW);
    // Per-lane ldmatrix offset: lanes 0-15 -> k-rows 0-15 of n-tile pair lo;
    // lanes 16-31 -> same k-rows, +16B (next n-tile).
    const uint32_t wlane = (uint32_t)(lane & 15) * WROWB + warp_n * 128 +
                           ((lane >> 4) & 1) * 16;

    // Prefetch W chunk 0.
    stage_w(0, sW, tid);
    asm volatile("cp.async.commit_group;\n" ::);

    if (tid < 128) sS[tid] = 0.0f;
    if (tid < 192) sWv[tid] = wv[tid];

    // Zero sUH (u-pad cols and h region must start clean), then fill u (fp16).
    for (int i = tid; i < 128 * UHSTR / 2; i += 256)
        ((uint32_t*)sUH)[i] = 0u;
    __syncthreads();
    for (int idx = tid; idx < NBB * F0C * DC; idx += 256) {
        int bl  = idx / (F0C * DC);
        int rem = idx - bl * (F0C * DC);
        int i = rem >> 4;
        int d = rem & 15;
        sUH[(bl * DC + d) * UHSTR + i] =
            __float2half_rn(x[(b0 + bl) * (F0C * DC) + rem]);
    }

    // Group metadata table.
    for (int gi = tid; gi < NGR; gi += 256) sMeta[gi] = group_meta(gi);
    __syncthreads();

    float acc[2][8][4];
#pragma unroll
    for (int rt = 0; rt < 2; ++rt)
#pragma unroll
        for (int nt = 0; nt < 8; ++nt)
#pragma unroll
            for (int q = 0; q < 4; ++q) acc[rt][nt][q] = 0.0f;

    for (int c = 0; c < NCHT; ++c) {
        asm volatile("cp.async.wait_group 0;\n" ::);   // W[c] resident
        __syncthreads();

        if (c == CH0) {
            // ---- Epilogue 0: cols 0..63 -> h (fp16); cols 64..127 -> dot.
#pragma unroll
            for (int rt = 0; rt < 2; ++rt) {
                int r0 = warp_m * 32 + rt * 16 + g;
                int r1 = r0 + 8;
                if (warp_n == 0) {
#pragma unroll
                    for (int nt = 0; nt < 8; ++nt) {
                        int n = nt * 8 + 2 * tig;
                        *(__half2*)(sUH + r0 * UHSTR + 48 + n) =
                            __floats2half2_rn(fmaxf(acc[rt][nt][0], 0.0f),
                                              fmaxf(acc[rt][nt][1], 0.0f));
                        *(__half2*)(sUH + r1 * UHSTR + 48 + n) =
                            __floats2half2_rn(fmaxf(acc[rt][nt][2], 0.0f),
                                              fmaxf(acc[rt][nt][3], 0.0f));
                    }
                } else {
                    float s0 = 0.0f, s1 = 0.0f;
#pragma unroll
                    for (int nt = 0; nt < 8; ++nt) {
                        int f = nt * 8 + 2 * tig;
                        float w0 = sWv[f], w1 = sWv[f + 1];
                        s0 += fmaxf(acc[rt][nt][0], 0.0f) * w0 +
                              fmaxf(acc[rt][nt][1], 0.0f) * w1;
                        s1 += fmaxf(acc[rt][nt][2], 0.0f) * w0 +
                              fmaxf(acc[rt][nt][3], 0.0f) * w1;
                    }
                    s0 += __shfl_xor_sync(0xffffffffu, s0, 1);
                    s0 += __shfl_xor_sync(0xffffffffu, s0, 2);
                    s1 += __shfl_xor_sync(0xffffffffu, s1, 1);
                    s1 += __shfl_xor_sync(0xffffffffu, s1, 2);
                    if (tig == 0) {
                        atomicAdd(&sS[r0], s0);
                        atomicAdd(&sS[r1], s1);
                    }
                }
            }
#pragma unroll
            for (int rt = 0; rt < 2; ++rt)
#pragma unroll
                for (int nt = 0; nt < 8; ++nt)
#pragma unroll
                    for (int q = 0; q < 4; ++q) acc[rt][nt][q] = 0.0f;
            __syncthreads();   // h visible before this chunk's builds
        }

        uint32_t m0 = sMeta[c * 8 + tig];
        uint32_t m1 = sMeta[c * 8 + 4 + tig];
        uint32_t wbuf = wbase_u32 + (uint32_t)(c & 1) * WBUFB + wlane;

        // Half 0: load + build. Then prefetch half-1 sources before MMAs.
        ASrc s0;
        load_src(sUH, R0, m0, s0);
        uint32_t a[2][2][4];
        build_a(s0, a);

        ASrc s1;
        load_src(sUH, R0, m1, s1);

        // Stage W[c+1] mid-chunk (2 buffers; barrier above protects reuse).
        if (c + 1 < NCHT)
            stage_w(c + 1, sW + ((c + 1) & 1) * WBUFB, tid);
        asm volatile("cp.async.commit_group;\n" ::);

        mma_half(wbuf, 0, a, acc);
        build_a(s1, a);
        mma_half(wbuf, 2, a, acc);
    }

    // ---- Epilogue 1: all 128 cols dotted with w[64:192].
#pragma unroll
    for (int rt = 0; rt < 2; ++rt) {
        int r0 = warp_m * 32 + rt * 16 + g;
        int r1 = r0 + 8;
        float s0 = 0.0f, s1 = 0.0f;
#pragma unroll
        for (int nt = 0; nt < 8; ++nt) {
            int f = 64 + warp_n * 64 + nt * 8 + 2 * tig;
            float w0 = sWv[f], w1 = sWv[f + 1];
            s0 += fmaxf(acc[rt][nt][0], 0.0f) * w0 +
                  fmaxf(acc[rt][nt][1], 0.0f) * w1;
            s1 += fmaxf(acc[rt][nt][2], 0.0f) * w0 +
                  fmaxf(acc[rt][nt][3], 0.0f) * w1;
        }
        s0 += __shfl_xor_sync(0xffffffffu, s0, 1);
        s0 += __shfl_xor_sync(0xffffffffu, s0, 2);
        s1 += __shfl_xor_sync(0xffffffffu, s1, 1);
        s1 += __shfl_xor_sync(0xffffffffu, s1, 2);
        if (tig == 0) {
            atomicAdd(&sS[r0], s0);
            atomicAdd(&sS[r1], s1);
        }
    }
    __syncthreads();

    // out[b] = bias + sum_d sS[bl*16 + d]
    if (tid < NBB) {
        float s = bias[0];
#pragma unroll
        for (int d = 0; d < DC; ++d) s += sS[tid * DC + d];
        out[b0 + tid] = s;
    }
}

// ---------------------------------------------------------------------------
extern "C" void kernel_launch(void* const* d_in, const int* in_sizes, int n_in,
                              void* d_out, int out_size) {
    (void)in_sizes; (void)n_in; (void)out_size;
    const float* x  = (const float*)d_in[0];
    const float* f0 = (const float*)d_in[1];
    const float* f1 = (const float*)d_in[2];
    const float* wv = (const float*)d_in[3];
    const float* bb = (const float*)d_in[4];
    float* out = (float*)d_out;

    cudaFuncSetAttribute(cin_kernel,
                         cudaFuncAttributeMaxDynamicSharedMemorySize,
                         SMEM_BYTES);

    fold_weights_kernel<<<(KTOT * 128 + 255) / 256, 256>>>(f0, f1);
    cin_kernel<<<512, 256, SMEM_BYTES>>>(x, wv, bb, out);
}